// round 8
// baseline (speedup 1.0000x reference)
#include <cuda_runtime.h>
#include <cuda_fp16.h>

#define TT 512
#define BB 512
#define DD 16
#define HH 64
#define G3 192
#define PT 32          // timesteps per precompute CTA
#define BK 16          // timesteps per staged block in rec kernel
#define NBK (TT / BK)
#define XGB (BK * G3 * 2)   // bytes per (row, block) = 6144

typedef unsigned long long ull;

__device__ __forceinline__ ull fma2(ull a, ull b, ull c) {
    ull d;
    asm("fma.rn.f32x2 %0, %1, %2, %3;" : "=l"(d) : "l"(a), "l"(b), "l"(c));
    return d;
}
__device__ __forceinline__ ull addf2(ull a, ull b) {
    ull d;
    asm("add.rn.f32x2 %0, %1, %2;" : "=l"(d) : "l"(a), "l"(b));
    return d;
}
__device__ __forceinline__ float hadd2(ull a) {
    return __uint_as_float((unsigned)a) + __uint_as_float((unsigned)(a >> 32));
}
__device__ __forceinline__ float tanha(float x) {
    float y;
    asm("tanh.approx.f32 %0, %1;" : "=f"(y) : "f"(x));
    return y;
}
__device__ __forceinline__ float siga(float x) {
    return fmaf(0.5f, tanha(0.5f * x), 0.5f);
}
__device__ __forceinline__ void cpa16(unsigned smem, const void* gmem) {
    asm volatile("cp.async.ca.shared.global [%0], [%1], 16;\n"
                 :: "r"(smem), "l"(gmem));
}
__device__ __forceinline__ void cpa_commit() {
    asm volatile("cp.async.commit_group;\n" ::: "memory");
}
__device__ __forceinline__ void cpa_wait1() {
    asm volatile("cp.async.wait_group 1;\n" ::: "memory");
}
__device__ __forceinline__ void barrow(int id) {   // named barrier, 64 threads
    asm volatile("bar.sync %0, 64;" :: "r"(id) : "memory");
}

// scratch: xg[b][t][g] = x·w_ih^T + b_ih (+ b_hh for r,z gates), fp16
__device__ __half g_xg[(size_t)BB * TT * G3];

// ---------------------------------------------------------------------------
// Kernel 1: xg precompute. r,z gates (g<128) also get b_hh folded in.
// ---------------------------------------------------------------------------
__global__ __launch_bounds__(G3)
void xg_kernel(const float* __restrict__ x,
               const float* __restrict__ w_ih,
               const float* __restrict__ b_ih,
               const float* __restrict__ b_hh)
{
    __shared__ __align__(16) float xs[PT][DD];
    const int g  = threadIdx.x;
    const int b  = blockIdx.y;
    const int t0 = blockIdx.x * PT;

    ulonglong2 wv[DD / 4];
    {
        const ulonglong2* p = (const ulonglong2*)(w_ih + g * DD);
        #pragma unroll
        for (int j = 0; j < DD / 4; j++) wv[j] = p[j];
    }
    float bias = b_ih[g];
    if (g < 2 * HH) bias += b_hh[g];      // fold recurrent bias for r,z gates

    for (int i = g; i < PT * DD / 4; i += G3)
        ((float4*)&xs[0][0])[i] =
            ((const float4*)(x + ((size_t)b * TT + t0) * DD))[i];
    __syncthreads();

    #pragma unroll 8
    for (int tt = 0; tt < PT; tt++) {
        const ulonglong2* xp = (const ulonglong2*)xs[tt];
        ull a0 = 0ull, a1 = 0ull;
        #pragma unroll
        for (int j = 0; j < DD / 4; j++) {
            ulonglong2 xv = xp[j];
            a0 = fma2(wv[j].x, xv.x, a0);
            a1 = fma2(wv[j].y, xv.y, a1);
        }
        g_xg[((size_t)b * TT + t0 + tt) * G3 + g] =
            __float2half_rn(hadd2(a0) + hadd2(a1) + bias);
    }
}

// ---------------------------------------------------------------------------
// Kernel 2: forward recurrence. CTA = 128 threads = 2 rows on all 4 SMSPs.
// Rows sync INDEPENDENTLY via named barriers (bar.sync 1+row, 64) so their
// chains interleave on the shared SMSPs; full __syncthreads only at 16-step
// block boundaries (cp.async buffer handoff). Thread owns one unit fully
// (192 weight regs, 64-wide dots, chains split 2x16).
// ---------------------------------------------------------------------------
__global__ __launch_bounds__(128, 2)
void gru_rec_kernel(const float* __restrict__ w_hh,
                    const float* __restrict__ b_hh,
                    const float* __restrict__ x,
                    const float* __restrict__ w_ih_b,
                    const float* __restrict__ b_ih_b,
                    const float* __restrict__ b_hh_b,
                    const float* __restrict__ fc_w,
                    const float* __restrict__ fc_b,
                    float* __restrict__ out)
{
    __shared__ __align__(16) float h_sh[2][2][HH];         // [parity][row][unit]
    __shared__ __align__(16) __half xg_sh[2][2][BK * G3];  // [buf][row][...]
    __shared__ float red_sh[2][HH];

    const int tid = threadIdx.x;
    const int row = tid >> 6;        // 0 or 1 (== warp-pair); warp-uniform
    const int u   = tid & 63;        // unit 0..63
    const int b   = blockIdx.x * 2 + row;

    // full rows r(u), z(u), n(u) of w_hh: 3 x 64 floats = 48 ulonglong2
    ulonglong2 w[3][16];
    {
        const int rows[3] = { u, HH + u, 2 * HH + u };
        #pragma unroll
        for (int i = 0; i < 3; i++) {
            const ulonglong2* p = (const ulonglong2*)(w_hh + rows[i] * HH);
            #pragma unroll
            for (int j = 0; j < 16; j++) w[i][j] = p[j];
        }
    }
    const float bhn = b_hh[2 * HH + u];

    const char* xg_g0 = (const char*)(g_xg + (size_t)(blockIdx.x * 2 + 0) * TT * G3);
    const char* xg_g1 = (const char*)(g_xg + (size_t)(blockIdx.x * 2 + 1) * TT * G3);
    const unsigned xg_sb = (unsigned)__cvta_generic_to_shared(&xg_sh[0][0][0]);

    float hold = 0.f;
    h_sh[0][row][u] = 0.f;

    // prologue: stage block 0 into buffer 0 (both rows)
    #pragma unroll
    for (int c = 0; c < 3; c++) {
        cpa16(xg_sb + (tid + 128 * c) * 16,         xg_g0 + (tid + 128 * c) * 16);
        cpa16(xg_sb + XGB + (tid + 128 * c) * 16,   xg_g1 + (tid + 128 * c) * 16);
    }
    cpa_commit();
    __syncthreads();

    int p = 0;
    for (int blk = 0; blk < NBK; ++blk) {
        if (blk + 1 < NBK) {
            unsigned dst = xg_sb + ((blk & 1) ? 0u : 2u * XGB);
            const char* s0 = xg_g0 + (size_t)(blk + 1) * XGB;
            const char* s1 = xg_g1 + (size_t)(blk + 1) * XGB;
            #pragma unroll
            for (int c = 0; c < 3; c++) {
                cpa16(dst + (tid + 128 * c) * 16,       s0 + (tid + 128 * c) * 16);
                cpa16(dst + XGB + (tid + 128 * c) * 16, s1 + (tid + 128 * c) * 16);
            }
        }
        cpa_commit();
        cpa_wait1();
        __syncthreads();   // buffer handoff: re-aligns the two rows per block

        const __half* xb = &xg_sh[blk & 1][row][0];

        #pragma unroll 4
        for (int tt = 0; tt < BK; ++tt) {
            float cur0 = __half2float(xb[tt * G3 + u]);
            float cur1 = __half2float(xb[tt * G3 + HH + u]);
            float cur2 = __half2float(xb[tt * G3 + 2 * HH + u]);

            const ulonglong2* hp = (const ulonglong2*)&h_sh[p][row][0];
            ull a0 = 0ull, a1 = 0ull, a2 = 0ull;
            ull c0 = 0ull, c1 = 0ull, c2 = 0ull;
            #pragma unroll
            for (int j = 0; j < 8; j++) {
                ulonglong2 hv = hp[j];
                a0 = fma2(w[0][j].x, hv.x, a0);
                a0 = fma2(w[0][j].y, hv.y, a0);
                a1 = fma2(w[1][j].x, hv.x, a1);
                a1 = fma2(w[1][j].y, hv.y, a1);
                a2 = fma2(w[2][j].x, hv.x, a2);
                a2 = fma2(w[2][j].y, hv.y, a2);
            }
            #pragma unroll
            for (int j = 8; j < 16; j++) {
                ulonglong2 hv = hp[j];
                c0 = fma2(w[0][j].x, hv.x, c0);
                c0 = fma2(w[0][j].y, hv.y, c0);
                c1 = fma2(w[1][j].x, hv.x, c1);
                c1 = fma2(w[1][j].y, hv.y, c1);
                c2 = fma2(w[2][j].x, hv.x, c2);
                c2 = fma2(w[2][j].y, hv.y, c2);
            }

            float rr = siga(cur0 + hadd2(addf2(a0, c0)));
            float zz = siga(cur1 + hadd2(addf2(a1, c1)));
            float nn = tanha(fmaf(rr, hadd2(addf2(a2, c2)) + bhn, cur2));
            hold = fmaf(zz, hold - nn, nn);     // (1-z)n + z h

            h_sh[p ^ 1][row][u] = hold;
            barrow(1 + row);                    // row-local barrier only
            p ^= 1;
        }
    }
    __syncthreads();

    // ---- epilogue: backward GRU = ONE step from h=0 on x[:,T-1,:]; then fc ----
    {
        const int j = u;
        const float* xl = x + ((size_t)b * TT + (TT - 1)) * DD;
        float xv[DD];
        #pragma unroll
        for (int k = 0; k < DD; k++) xv[k] = __ldg(xl + k);

        float ar  = __ldg(b_ih_b + j)          + __ldg(b_hh_b + j);
        float az  = __ldg(b_ih_b + HH + j)     + __ldg(b_hh_b + HH + j);
        float anx = __ldg(b_ih_b + 2 * HH + j);
        float anh = __ldg(b_hh_b + 2 * HH + j);
        const float* wr = w_ih_b + (size_t)j * DD;
        const float* wz = w_ih_b + (size_t)(HH + j) * DD;
        const float* wn = w_ih_b + (size_t)(2 * HH + j) * DD;
        #pragma unroll
        for (int k = 0; k < DD; k++) {
            ar  += __ldg(wr + k) * xv[k];
            az  += __ldg(wz + k) * xv[k];
            anx += __ldg(wn + k) * xv[k];
        }
        float rb = siga(ar);
        float zb = siga(az);
        float nb = tanha(anx + rb * anh);
        float hb = (1.f - zb) * nb;            // h_prev = 0

        red_sh[row][j] = hold * __ldg(fc_w + j) + hb * __ldg(fc_w + HH + j);
    }
    __syncthreads();
    if (tid < 2) {
        float sum = __ldg(fc_b);
        #pragma unroll
        for (int k = 0; k < HH; k++) sum += red_sh[tid][k];
        out[blockIdx.x * 2 + tid] = sum;
    }
}

extern "C" void kernel_launch(void* const* d_in, const int* in_sizes, int n_in,
                              void* d_out, int out_size)
{
    const float* x      = (const float*)d_in[0];
    const float* w_ih_f = (const float*)d_in[1];
    const float* w_hh_f = (const float*)d_in[2];
    const float* b_ih_f = (const float*)d_in[3];
    const float* b_hh_f = (const float*)d_in[4];
    const float* w_ih_b = (const float*)d_in[5];
    /* d_in[6] = w_hh_b unused: backward direction starts from h=0 */
    const float* b_ih_b = (const float*)d_in[7];
    const float* b_hh_b = (const float*)d_in[8];
    const float* fc_w   = (const float*)d_in[9];
    const float* fc_b   = (const float*)d_in[10];

    xg_kernel<<<dim3(TT / PT, BB), G3>>>(x, w_ih_f, b_ih_f, b_hh_f);
    gru_rec_kernel<<<BB / 2, 128>>>(w_hh_f, b_hh_f, x,
                                    w_ih_b, b_ih_b, b_hh_b,
                                    fc_w, fc_b, (float*)d_out);
}

// round 9
// speedup vs baseline: 1.0018x; 1.0018x over previous
#include <cuda_runtime.h>
#include <cuda_fp16.h>

#define TT 512
#define BB 512
#define DD 16
#define HH 64
#define G3 192
#define PT 32          // timesteps per precompute CTA
#define BK 16          // timesteps per staged block in rec kernel
#define NBK (TT / BK)
#define XGB (BK * G3 * 2)   // bytes per (row, block) = 6144

typedef unsigned long long ull;

__device__ __forceinline__ ull fma2(ull a, ull b, ull c) {
    ull d;
    asm("fma.rn.f32x2 %0, %1, %2, %3;" : "=l"(d) : "l"(a), "l"(b), "l"(c));
    return d;
}
__device__ __forceinline__ ull addf2(ull a, ull b) {
    ull d;
    asm("add.rn.f32x2 %0, %1, %2;" : "=l"(d) : "l"(a), "l"(b));
    return d;
}
__device__ __forceinline__ float hadd2(ull a) {
    return __uint_as_float((unsigned)a) + __uint_as_float((unsigned)(a >> 32));
}
__device__ __forceinline__ float tanha(float x) {
    float y;
    asm("tanh.approx.f32 %0, %1;" : "=f"(y) : "f"(x));
    return y;
}
__device__ __forceinline__ float siga(float x) {
    return fmaf(0.5f, tanha(0.5f * x), 0.5f);
}
__device__ __forceinline__ void cpa16(unsigned smem, const void* gmem) {
    asm volatile("cp.async.ca.shared.global [%0], [%1], 16;\n"
                 :: "r"(smem), "l"(gmem));
}
__device__ __forceinline__ void cpa_commit() {
    asm volatile("cp.async.commit_group;\n" ::: "memory");
}
__device__ __forceinline__ void cpa_wait1() {
    asm volatile("cp.async.wait_group 1;\n" ::: "memory");
}
__device__ __forceinline__ void barrow(int id) {   // named barrier, 64 threads
    asm volatile("bar.sync %0, 64;" :: "r"(id) : "memory");
}

// scratch: xg[b][t][g] = x·w_ih^T + b_ih (+ b_hh for r,z gates), fp16
__device__ __half g_xg[(size_t)BB * TT * G3];

// ---------------------------------------------------------------------------
// Kernel 1: xg precompute. r,z gates (g<128) also get b_hh folded in.
// ---------------------------------------------------------------------------
__global__ __launch_bounds__(G3)
void xg_kernel(const float* __restrict__ x,
               const float* __restrict__ w_ih,
               const float* __restrict__ b_ih,
               const float* __restrict__ b_hh)
{
    __shared__ __align__(16) float xs[PT][DD];
    const int g  = threadIdx.x;
    const int b  = blockIdx.y;
    const int t0 = blockIdx.x * PT;

    ulonglong2 wv[DD / 4];
    {
        const ulonglong2* p = (const ulonglong2*)(w_ih + g * DD);
        #pragma unroll
        for (int j = 0; j < DD / 4; j++) wv[j] = p[j];
    }
    float bias = b_ih[g];
    if (g < 2 * HH) bias += b_hh[g];      // fold recurrent bias for r,z gates

    for (int i = g; i < PT * DD / 4; i += G3)
        ((float4*)&xs[0][0])[i] =
            ((const float4*)(x + ((size_t)b * TT + t0) * DD))[i];
    __syncthreads();

    #pragma unroll 8
    for (int tt = 0; tt < PT; tt++) {
        const ulonglong2* xp = (const ulonglong2*)xs[tt];
        ull a0 = 0ull, a1 = 0ull;
        #pragma unroll
        for (int j = 0; j < DD / 4; j++) {
            ulonglong2 xv = xp[j];
            a0 = fma2(wv[j].x, xv.x, a0);
            a1 = fma2(wv[j].y, xv.y, a1);
        }
        g_xg[((size_t)b * TT + t0 + tt) * G3 + g] =
            __float2half_rn(hadd2(a0) + hadd2(a1) + bias);
    }
}

// ---------------------------------------------------------------------------
// Kernel 2: forward recurrence. CTA = 128 threads = 2 FULLY DECOUPLED rows:
// row 0 = warps 0,1 (SMSP 0,1), row 1 = warps 2,3 (SMSP 2,3). Each row stages
// its own xg (cp.async) and syncs ONLY on its named barrier — no CTA-wide
// sync until the epilogue. CTAs with blockIdx >= 148 (second resident CTA on
// an SM) run a one-time ~360-cycle delay to break cross-CTA phase lockstep,
// so one CTA's dot-issue phase overlaps the other's serial phase.
// ---------------------------------------------------------------------------
__global__ __launch_bounds__(128, 2)
void gru_rec_kernel(const float* __restrict__ w_hh,
                    const float* __restrict__ b_hh,
                    const float* __restrict__ x,
                    const float* __restrict__ w_ih_b,
                    const float* __restrict__ b_ih_b,
                    const float* __restrict__ b_hh_b,
                    const float* __restrict__ fc_w,
                    const float* __restrict__ fc_b,
                    float* __restrict__ out)
{
    __shared__ __align__(16) float h_sh[2][2][HH];         // [parity][row][unit]
    __shared__ __align__(16) __half xg_sh[2][2][BK * G3];  // [buf][row][...]
    __shared__ float red_sh[2][HH];

    const int tid = threadIdx.x;
    const int row = tid >> 6;        // 0 or 1; row r uses SMSPs {2r, 2r+1}
    const int u   = tid & 63;        // unit 0..63
    const int b   = blockIdx.x * 2 + row;

    // full rows r(u), z(u), n(u) of w_hh: 3 x 64 floats = 48 ulonglong2
    ulonglong2 w[3][16];
    {
        const int rows[3] = { u, HH + u, 2 * HH + u };
        #pragma unroll
        for (int i = 0; i < 3; i++) {
            const ulonglong2* p = (const ulonglong2*)(w_hh + rows[i] * HH);
            #pragma unroll
            for (int j = 0; j < 16; j++) w[i][j] = p[j];
        }
    }
    const float bhn = b_hh[2 * HH + u];

    // phase-stagger: delay the second resident CTA on each SM (~360 cyc)
    if (blockIdx.x >= 148) {
        float acc = (float)(blockIdx.x + u);
        #pragma unroll 1
        for (int i = 0; i < 90; i++)
            asm volatile("fma.rn.f32 %0, %0, 0f3F800001, 0f00000001;" : "+f"(acc));
        if (acc == 1.2345678e-35f) red_sh[0][0] = acc;   // never true; keeps dep
    }

    // row-local xg staging state
    const char* xg_g = (const char*)(g_xg + (size_t)b * TT * G3);
    const unsigned xg_row = (unsigned)__cvta_generic_to_shared(&xg_sh[0][row][0]);
    // buffer bb at offset bb * (2*XGB); 6 chunks of 16B per thread per block

    float hold = 0.f;
    h_sh[0][row][u] = 0.f;

    // prologue: stage block 0 into buffer 0 (own row only)
    #pragma unroll
    for (int c = 0; c < 6; c++)
        cpa16(xg_row + (u + 64 * c) * 16, xg_g + (u + 64 * c) * 16);
    cpa_commit();
    barrow(1 + row);

    int p = 0;
    for (int blk = 0; blk < NBK; ++blk) {
        if (blk + 1 < NBK) {
            unsigned dst = xg_row + ((blk & 1) ? 0u : 2u * XGB);
            const char* src = xg_g + (size_t)(blk + 1) * XGB;
            #pragma unroll
            for (int c = 0; c < 6; c++)
                cpa16(dst + (u + 64 * c) * 16, src + (u + 64 * c) * 16);
        }
        cpa_commit();
        cpa_wait1();
        barrow(1 + row);    // all 64 row-threads have waited -> row buffer ready

        const __half* xb = &xg_sh[blk & 1][row][0];

        #pragma unroll 4
        for (int tt = 0; tt < BK; ++tt) {
            float cur0 = __half2float(xb[tt * G3 + u]);
            float cur1 = __half2float(xb[tt * G3 + HH + u]);
            float cur2 = __half2float(xb[tt * G3 + 2 * HH + u]);

            const ulonglong2* hp = (const ulonglong2*)&h_sh[p][row][0];

            // r and z gates first (start sigmoids under the n-gate issue)
            ull a0 = 0ull, a1 = 0ull, c0 = 0ull, c1 = 0ull;
            #pragma unroll
            for (int j = 0; j < 8; j++) {
                ulonglong2 hv = hp[j];
                a0 = fma2(w[0][j].x, hv.x, a0);
                a0 = fma2(w[0][j].y, hv.y, a0);
                a1 = fma2(w[1][j].x, hv.x, a1);
                a1 = fma2(w[1][j].y, hv.y, a1);
            }
            #pragma unroll
            for (int j = 8; j < 16; j++) {
                ulonglong2 hv = hp[j];
                c0 = fma2(w[0][j].x, hv.x, c0);
                c0 = fma2(w[0][j].y, hv.y, c0);
                c1 = fma2(w[1][j].x, hv.x, c1);
                c1 = fma2(w[1][j].y, hv.y, c1);
            }
            float rr = siga(cur0 + hadd2(addf2(a0, c0)));
            float zz = siga(cur1 + hadd2(addf2(a1, c1)));

            // n gate
            ull a2 = 0ull, c2 = 0ull;
            #pragma unroll
            for (int j = 0; j < 8; j++) {
                ulonglong2 hv = hp[j];
                a2 = fma2(w[2][j].x, hv.x, a2);
                a2 = fma2(w[2][j].y, hv.y, a2);
            }
            #pragma unroll
            for (int j = 8; j < 16; j++) {
                ulonglong2 hv = hp[j];
                c2 = fma2(w[2][j].x, hv.x, c2);
                c2 = fma2(w[2][j].y, hv.y, c2);
            }
            float nn = tanha(fmaf(rr, hadd2(addf2(a2, c2)) + bhn, cur2));
            hold = fmaf(zz, hold - nn, nn);     // (1-z)n + z h

            h_sh[p ^ 1][row][u] = hold;
            barrow(1 + row);                    // row-local barrier only
            p ^= 1;
        }
    }
    __syncthreads();

    // ---- epilogue: backward GRU = ONE step from h=0 on x[:,T-1,:]; then fc ----
    {
        const int j = u;
        const float* xl = x + ((size_t)b * TT + (TT - 1)) * DD;
        float xv[DD];
        #pragma unroll
        for (int k = 0; k < DD; k++) xv[k] = __ldg(xl + k);

        float ar  = __ldg(b_ih_b + j)          + __ldg(b_hh_b + j);
        float az  = __ldg(b_ih_b + HH + j)     + __ldg(b_hh_b + HH + j);
        float anx = __ldg(b_ih_b + 2 * HH + j);
        float anh = __ldg(b_hh_b + 2 * HH + j);
        const float* wr = w_ih_b + (size_t)j * DD;
        const float* wz = w_ih_b + (size_t)(HH + j) * DD;
        const float* wn = w_ih_b + (size_t)(2 * HH + j) * DD;
        #pragma unroll
        for (int k = 0; k < DD; k++) {
            ar  += __ldg(wr + k) * xv[k];
            az  += __ldg(wz + k) * xv[k];
            anx += __ldg(wn + k) * xv[k];
        }
        float rb = siga(ar);
        float zb = siga(az);
        float nb = tanha(anx + rb * anh);
        float hb = (1.f - zb) * nb;            // h_prev = 0

        red_sh[row][j] = hold * __ldg(fc_w + j) + hb * __ldg(fc_w + HH + j);
    }
    __syncthreads();
    if (tid < 2) {
        float sum = __ldg(fc_b);
        #pragma unroll
        for (int k = 0; k < HH; k++) sum += red_sh[tid][k];
        out[blockIdx.x * 2 + tid] = sum;
    }
}

extern "C" void kernel_launch(void* const* d_in, const int* in_sizes, int n_in,
                              void* d_out, int out_size)
{
    const float* x      = (const float*)d_in[0];
    const float* w_ih_f = (const float*)d_in[1];
    const float* w_hh_f = (const float*)d_in[2];
    const float* b_ih_f = (const float*)d_in[3];
    const float* b_hh_f = (const float*)d_in[4];
    const float* w_ih_b = (const float*)d_in[5];
    /* d_in[6] = w_hh_b unused: backward direction starts from h=0 */
    const float* b_ih_b = (const float*)d_in[7];
    const float* b_hh_b = (const float*)d_in[8];
    const float* fc_w   = (const float*)d_in[9];
    const float* fc_b   = (const float*)d_in[10];

    xg_kernel<<<dim3(TT / PT, BB), G3>>>(x, w_ih_f, b_ih_f, b_hh_f);
    gru_rec_kernel<<<BB / 2, 128>>>(w_hh_f, b_hh_f, x,
                                    w_ih_b, b_ih_b, b_hh_b,
                                    fc_w, fc_b, (float*)d_out);
}

// round 10
// speedup vs baseline: 1.0734x; 1.0714x over previous
#include <cuda_runtime.h>
#include <cuda_fp16.h>

#define TT 512
#define BB 512
#define DD 16
#define HH 64
#define PT 64          // timesteps per precompute CTA
#define BK 8           // timesteps per staged block in rec kernel
#define NBK (TT / BK)
#define ROWBLK (BK * 256 * 2)   // bytes per (row, block) = 4096

typedef unsigned long long ull;

__device__ __forceinline__ ull fma2(ull a, ull b, ull c) {
    ull d;
    asm("fma.rn.f32x2 %0, %1, %2, %3;" : "=l"(d) : "l"(a), "l"(b), "l"(c));
    return d;
}
__device__ __forceinline__ ull addf2(ull a, ull b) {
    ull d;
    asm("add.rn.f32x2 %0, %1, %2;" : "=l"(d) : "l"(a), "l"(b));
    return d;
}
__device__ __forceinline__ float hadd2(ull a) {
    return __uint_as_float((unsigned)a) + __uint_as_float((unsigned)(a >> 32));
}
__device__ __forceinline__ float tanha(float x) {
    float y;
    asm("tanh.approx.f32 %0, %1;" : "=f"(y) : "f"(x));
    return y;
}
__device__ __forceinline__ float siga(float x) {
    return fmaf(0.5f, tanha(0.5f * x), 0.5f);
}
__device__ __forceinline__ void cpa16(unsigned smem, const void* gmem) {
    asm volatile("cp.async.ca.shared.global [%0], [%1], 16;\n"
                 :: "r"(smem), "l"(gmem));
}
__device__ __forceinline__ void cpa_commit() {
    asm volatile("cp.async.commit_group;\n" ::: "memory");
}
__device__ __forceinline__ void cpa_wait1() {
    asm volatile("cp.async.wait_group 1;\n" ::: "memory");
}
__device__ __forceinline__ void barpair(int id) {  // named barrier, 64 threads
    asm volatile("bar.sync %0, 64;" :: "r"(id) : "memory");
}

// scratch: xg[b][t][u][{r,z,n,pad}] fp16; r,z include b_ih+b_hh, n includes b_ih
__device__ __half g_xg[(size_t)BB * TT * 256];

// ---------------------------------------------------------------------------
// Kernel 1: xg precompute. 128-thr CTA (all 4 SMSPs): thread = (unit u,
// t-half). Each thread computes ALL 3 gates of unit u (x loads amortized),
// writes packed {r,z,n,0} as one 8-byte store.
// ---------------------------------------------------------------------------
__global__ __launch_bounds__(128)
void xg_kernel(const float* __restrict__ x,
               const float* __restrict__ w_ih,
               const float* __restrict__ b_ih,
               const float* __restrict__ b_hh)
{
    __shared__ __align__(16) float xs[PT][DD];   // 4KB
    const int tid = threadIdx.x;
    const int u   = tid & 63;
    const int th  = tid >> 6;          // t-half 0/1
    const int b   = blockIdx.y;
    const int t0  = blockIdx.x * PT;

    ulonglong2 wv[3][DD / 4];
    {
        const int rows[3] = { u, HH + u, 2 * HH + u };
        #pragma unroll
        for (int g = 0; g < 3; g++) {
            const ulonglong2* p = (const ulonglong2*)(w_ih + rows[g] * DD);
            #pragma unroll
            for (int j = 0; j < DD / 4; j++) wv[g][j] = p[j];
        }
    }
    const float br = b_ih[u]          + b_hh[u];
    const float bz = b_ih[HH + u]     + b_hh[HH + u];
    const float bn = b_ih[2 * HH + u];

    for (int i = tid; i < PT * DD / 4; i += 128)
        ((float4*)&xs[0][0])[i] =
            ((const float4*)(x + ((size_t)b * TT + t0) * DD))[i];
    __syncthreads();

    #pragma unroll 4
    for (int k = 0; k < PT / 2; k++) {
        const int tt = th * (PT / 2) + k;
        const ulonglong2* xp = (const ulonglong2*)xs[tt];
        ull a0 = 0ull, a1 = 0ull, a2 = 0ull;
        #pragma unroll
        for (int j = 0; j < DD / 4; j++) {
            ulonglong2 xv = xp[j];
            a0 = fma2(wv[0][j].x, xv.x, a0);
            a0 = fma2(wv[0][j].y, xv.y, a0);
            a1 = fma2(wv[1][j].x, xv.x, a1);
            a1 = fma2(wv[1][j].y, xv.y, a1);
            a2 = fma2(wv[2][j].x, xv.x, a2);
            a2 = fma2(wv[2][j].y, xv.y, a2);
        }
        __half2 rz = __floats2half2_rn(hadd2(a0) + br, hadd2(a1) + bz);
        __half2 n0 = __floats2half2_rn(hadd2(a2) + bn, 0.f);
        uint2 pkt;
        pkt.x = *reinterpret_cast<unsigned*>(&rz);
        pkt.y = *reinterpret_cast<unsigned*>(&n0);
        *reinterpret_cast<uint2*>(g_xg + ((size_t)(b * TT + t0 + tt) * 256) + u * 4) = pkt;
    }
}

// ---------------------------------------------------------------------------
// Kernel 2: forward recurrence. Grid 128, CTA = 128 threads = 4 rows.
// Warp-pair p (threads 64p..64p+63, SMSPs {2p,2p+1}) owns rows 2p, 2p+1 and
// INTERLEAVES them in-thread (shared weight regs): dotA issue hides nothing,
// dotB issue hides A's chain tail, only B's tail + pair-barrier exposed.
// Pairs are fully private (own cp.async staging, own named barrier).
// ---------------------------------------------------------------------------
__global__ __launch_bounds__(128, 1)
void gru_rec_kernel(const float* __restrict__ w_hh,
                    const float* __restrict__ b_hh,
                    const float* __restrict__ x,
                    const float* __restrict__ w_ih_b,
                    const float* __restrict__ b_ih_b,
                    const float* __restrict__ b_hh_b,
                    const float* __restrict__ fc_w,
                    const float* __restrict__ fc_b,
                    float* __restrict__ out)
{
    __shared__ __align__(16) float h_sh[2][4][HH];          // [parity][row][unit]
    __shared__ __align__(16) __half xg_sh[2][4][BK * 256];  // 2 x 16KB
    __shared__ float red_sh[4][HH];

    const int tid  = threadIdx.x;
    const int pair = tid >> 6;       // 0/1 ; rows 2*pair, 2*pair+1
    const int u    = tid & 63;
    const int rA   = 2 * pair, rB = 2 * pair + 1;
    const int b0   = blockIdx.x * 4;

    ulonglong2 w[3][16];
    {
        const int rows[3] = { u, HH + u, 2 * HH + u };
        #pragma unroll
        for (int i = 0; i < 3; i++) {
            const ulonglong2* p = (const ulonglong2*)(w_hh + rows[i] * HH);
            #pragma unroll
            for (int j = 0; j < 16; j++) w[i][j] = p[j];
        }
    }
    const float bhn = b_hh[2 * HH + u];

    const char* xgA = (const char*)(g_xg + (size_t)(b0 + rA) * TT * 256);
    const char* xgB = (const char*)(g_xg + (size_t)(b0 + rB) * TT * 256);
    const unsigned sA = (unsigned)__cvta_generic_to_shared(&xg_sh[0][rA][0]);
    const unsigned sB = (unsigned)__cvta_generic_to_shared(&xg_sh[0][rB][0]);
    const unsigned BUFSTRIDE = 4 * ROWBLK;   // xg_sh[1] - xg_sh[0] = 16384 B

    float holdA = 0.f, holdB = 0.f;
    h_sh[0][rA][u] = 0.f;
    h_sh[0][rB][u] = 0.f;

    // prologue: stage block 0 (own rows; 4 x 16B chunks per row per thread)
    #pragma unroll
    for (int c = 0; c < 4; c++) {
        cpa16(sA + (u + 64 * c) * 16, xgA + (u + 64 * c) * 16);
        cpa16(sB + (u + 64 * c) * 16, xgB + (u + 64 * c) * 16);
    }
    cpa_commit();
    barpair(1 + pair);

    int p = 0;
    for (int blk = 0; blk < NBK; ++blk) {
        if (blk + 1 < NBK) {
            unsigned off = (blk & 1) ? 0u : BUFSTRIDE;
            const char* gA = xgA + (size_t)(blk + 1) * ROWBLK;
            const char* gB = xgB + (size_t)(blk + 1) * ROWBLK;
            #pragma unroll
            for (int c = 0; c < 4; c++) {
                cpa16(sA + off + (u + 64 * c) * 16, gA + (u + 64 * c) * 16);
                cpa16(sB + off + (u + 64 * c) * 16, gB + (u + 64 * c) * 16);
            }
        }
        cpa_commit();
        cpa_wait1();
        barpair(1 + pair);

        const __half* xbA = &xg_sh[blk & 1][rA][0];
        const __half* xbB = &xg_sh[blk & 1][rB][0];

        #pragma unroll 4
        for (int tt = 0; tt < BK; ++tt) {
            uint2 ga = *reinterpret_cast<const uint2*>(xbA + tt * 256 + u * 4);
            uint2 gb = *reinterpret_cast<const uint2*>(xbB + tt * 256 + u * 4);
            float2 rzA = __half22float2(*reinterpret_cast<__half2*>(&ga.x));
            float  xnA = __half2float(*reinterpret_cast<__half*>(&ga.y));
            float2 rzB = __half22float2(*reinterpret_cast<__half2*>(&gb.x));
            float  xnB = __half2float(*reinterpret_cast<__half*>(&gb.y));

            // dot A (row 2*pair)
            const ulonglong2* hpA = (const ulonglong2*)&h_sh[p][rA][0];
            ull a0 = 0ull, a1 = 0ull, a2 = 0ull, c0 = 0ull, c1 = 0ull, c2 = 0ull;
            #pragma unroll
            for (int j = 0; j < 8; j++) {
                ulonglong2 hv = hpA[j];
                a0 = fma2(w[0][j].x, hv.x, a0); a0 = fma2(w[0][j].y, hv.y, a0);
                a1 = fma2(w[1][j].x, hv.x, a1); a1 = fma2(w[1][j].y, hv.y, a1);
                a2 = fma2(w[2][j].x, hv.x, a2); a2 = fma2(w[2][j].y, hv.y, a2);
            }
            #pragma unroll
            for (int j = 8; j < 16; j++) {
                ulonglong2 hv = hpA[j];
                c0 = fma2(w[0][j].x, hv.x, c0); c0 = fma2(w[0][j].y, hv.y, c0);
                c1 = fma2(w[1][j].x, hv.x, c1); c1 = fma2(w[1][j].y, hv.y, c1);
                c2 = fma2(w[2][j].x, hv.x, c2); c2 = fma2(w[2][j].y, hv.y, c2);
            }

            // dot B (row 2*pair+1) — issues while A's chains resolve
            const ulonglong2* hpB = (const ulonglong2*)&h_sh[p][rB][0];
            ull d0 = 0ull, d1 = 0ull, d2 = 0ull, e0 = 0ull, e1 = 0ull, e2 = 0ull;
            #pragma unroll
            for (int j = 0; j < 8; j++) {
                ulonglong2 hv = hpB[j];
                d0 = fma2(w[0][j].x, hv.x, d0); d0 = fma2(w[0][j].y, hv.y, d0);
                d1 = fma2(w[1][j].x, hv.x, d1); d1 = fma2(w[1][j].y, hv.y, d1);
                d2 = fma2(w[2][j].x, hv.x, d2); d2 = fma2(w[2][j].y, hv.y, d2);
            }
            #pragma unroll
            for (int j = 8; j < 16; j++) {
                ulonglong2 hv = hpB[j];
                e0 = fma2(w[0][j].x, hv.x, e0); e0 = fma2(w[0][j].y, hv.y, e0);
                e1 = fma2(w[1][j].x, hv.x, e1); e1 = fma2(w[1][j].y, hv.y, e1);
                e2 = fma2(w[2][j].x, hv.x, e2); e2 = fma2(w[2][j].y, hv.y, e2);
            }

            // finalize A
            {
                float rr = siga(rzA.x + hadd2(addf2(a0, c0)));
                float zz = siga(rzA.y + hadd2(addf2(a1, c1)));
                float nn = tanha(fmaf(rr, hadd2(addf2(a2, c2)) + bhn, xnA));
                holdA = fmaf(zz, holdA - nn, nn);
                h_sh[p ^ 1][rA][u] = holdA;
            }
            // finalize B
            {
                float rr = siga(rzB.x + hadd2(addf2(d0, e0)));
                float zz = siga(rzB.y + hadd2(addf2(d1, e1)));
                float nn = tanha(fmaf(rr, hadd2(addf2(d2, e2)) + bhn, xnB));
                holdB = fmaf(zz, holdB - nn, nn);
                h_sh[p ^ 1][rB][u] = holdB;
            }
            barpair(1 + pair);
            p ^= 1;
        }
    }
    __syncthreads();

    // ---- epilogue: backward GRU = ONE step from h=0 on x[:,T-1,:]; then fc ----
    #pragma unroll
    for (int k = 0; k < 2; k++) {
        const int r = 2 * pair + k;
        const int b = b0 + r;
        const float hold = k ? holdB : holdA;
        const int j = u;
        const float* xl = x + ((size_t)b * TT + (TT - 1)) * DD;
        float xv[DD];
        #pragma unroll
        for (int kk = 0; kk < DD; kk++) xv[kk] = __ldg(xl + kk);

        float ar  = __ldg(b_ih_b + j)          + __ldg(b_hh_b + j);
        float az  = __ldg(b_ih_b + HH + j)     + __ldg(b_hh_b + HH + j);
        float anx = __ldg(b_ih_b + 2 * HH + j);
        float anh = __ldg(b_hh_b + 2 * HH + j);
        const float* wr = w_ih_b + (size_t)j * DD;
        const float* wz = w_ih_b + (size_t)(HH + j) * DD;
        const float* wn = w_ih_b + (size_t)(2 * HH + j) * DD;
        #pragma unroll
        for (int kk = 0; kk < DD; kk++) {
            ar  += __ldg(wr + kk) * xv[kk];
            az  += __ldg(wz + kk) * xv[kk];
            anx += __ldg(wn + kk) * xv[kk];
        }
        float rb = siga(ar);
        float zb = siga(az);
        float nb = tanha(anx + rb * anh);
        float hb = (1.f - zb) * nb;            // h_prev = 0

        red_sh[r][j] = hold * __ldg(fc_w + j) + hb * __ldg(fc_w + HH + j);
    }
    __syncthreads();
    if (tid < 4) {
        float sum = __ldg(fc_b);
        #pragma unroll
        for (int k = 0; k < HH; k++) sum += red_sh[tid][k];
        out[b0 + tid] = sum;
    }
}

extern "C" void kernel_launch(void* const* d_in, const int* in_sizes, int n_in,
                              void* d_out, int out_size)
{
    const float* x      = (const float*)d_in[0];
    const float* w_ih_f = (const float*)d_in[1];
    const float* w_hh_f = (const float*)d_in[2];
    const float* b_ih_f = (const float*)d_in[3];
    const float* b_hh_f = (const float*)d_in[4];
    const float* w_ih_b = (const float*)d_in[5];
    /* d_in[6] = w_hh_b unused: backward direction starts from h=0 */
    const float* b_ih_b = (const float*)d_in[7];
    const float* b_hh_b = (const float*)d_in[8];
    const float* fc_w   = (const float*)d_in[9];
    const float* fc_b   = (const float*)d_in[10];

    xg_kernel<<<dim3(TT / PT, BB), 128>>>(x, w_ih_f, b_ih_f, b_hh_f);
    gru_rec_kernel<<<BB / 4, 128>>>(w_hh_f, b_hh_f, x,
                                    w_ih_b, b_ih_b, b_hh_b,
                                    fc_w, fc_b, (float*)d_out);
}